// round 1
// baseline (speedup 1.0000x reference)
#include <cuda_runtime.h>

#define BATCH 32768
#define NVEC  4096
#define EDIM  256
#define KNN   20

#define BM 128
#define BN 128
#define BK 16
#define TM 8
#define TN 8
// 256 threads: 16 (tx, n-dir) x 16 (ty, m-dir)

__device__ unsigned long long g_best[BATCH];

__global__ void init_best_kernel() {
    int i = blockIdx.x * blockDim.x + threadIdx.x;
    if (i < BATCH) g_best[i] = 0xFFFFFFFFFFFFFFFFULL;
}

__device__ __forceinline__ unsigned int float_to_sortable(float f) {
    unsigned int u = __float_as_uint(f);
    return (u & 0x80000000u) ? ~u : (u | 0x80000000u);
}

__global__ __launch_bounds__(256, 2)
void dist_argmin_kernel(const float* __restrict__ x, const float* __restrict__ W) {
    __shared__ float As[BK][BM];   // K-transposed: As[k][m]
    __shared__ float Bs[BK][BN];   // K-transposed: Bs[k][n]

    const int m0 = blockIdx.y * BM;
    const int n0 = blockIdx.x * BN;
    const int tid = threadIdx.x;
    const int tx = tid & 15;   // n
    const int ty = tid >> 4;   // m

    // loaders: 128 rows x 16 k; each thread: 1 row, 8 k (two float4)
    const int l_row  = tid >> 1;            // 0..127
    const int l_koff = (tid & 1) * 8;       // 0 or 8

    const float* aP = x + (long long)(m0 + l_row) * EDIM + l_koff;
    const float* bP = W + (long long)(n0 + l_row) * EDIM + l_koff;

    float acc[TM][TN];
#pragma unroll
    for (int i = 0; i < TM; i++)
#pragma unroll
        for (int j = 0; j < TN; j++) acc[i][j] = 0.0f;

    // prefetch first tile
    float4 pa0 = *(const float4*)(aP + 0);
    float4 pa1 = *(const float4*)(aP + 4);
    float4 pb0 = *(const float4*)(bP + 0);
    float4 pb1 = *(const float4*)(bP + 4);

    for (int k0 = 0; k0 < EDIM; k0 += BK) {
        __syncthreads();
        // store transposed (scatter scalars)
        As[l_koff + 0][l_row] = pa0.x;
        As[l_koff + 1][l_row] = pa0.y;
        As[l_koff + 2][l_row] = pa0.z;
        As[l_koff + 3][l_row] = pa0.w;
        As[l_koff + 4][l_row] = pa1.x;
        As[l_koff + 5][l_row] = pa1.y;
        As[l_koff + 6][l_row] = pa1.z;
        As[l_koff + 7][l_row] = pa1.w;
        Bs[l_koff + 0][l_row] = pb0.x;
        Bs[l_koff + 1][l_row] = pb0.y;
        Bs[l_koff + 2][l_row] = pb0.z;
        Bs[l_koff + 3][l_row] = pb0.w;
        Bs[l_koff + 4][l_row] = pb1.x;
        Bs[l_koff + 5][l_row] = pb1.y;
        Bs[l_koff + 6][l_row] = pb1.z;
        Bs[l_koff + 7][l_row] = pb1.w;
        __syncthreads();

        if (k0 + BK < EDIM) {
            pa0 = *(const float4*)(aP + k0 + BK + 0);
            pa1 = *(const float4*)(aP + k0 + BK + 4);
            pb0 = *(const float4*)(bP + k0 + BK + 0);
            pb1 = *(const float4*)(bP + k0 + BK + 4);
        }

#pragma unroll
        for (int k = 0; k < BK; k++) {
            float4 a0 = *(const float4*)&As[k][ty * TM];
            float4 a1 = *(const float4*)&As[k][ty * TM + 4];
            float4 b0 = *(const float4*)&Bs[k][tx * TN];
            float4 b1 = *(const float4*)&Bs[k][tx * TN + 4];
            float a[TM] = {a0.x, a0.y, a0.z, a0.w, a1.x, a1.y, a1.z, a1.w};
            float b[TN] = {b0.x, b0.y, b0.z, b0.w, b1.x, b1.y, b1.z, b1.w};
#pragma unroll
            for (int i = 0; i < TM; i++)
#pragma unroll
                for (int j = 0; j < TN; j++)
                    acc[i][j] = fmaf(a[i], b[j], acc[i][j]);
        }
    }

    // Epilogue: per-row argmin of this 128x128 tile, combine via atomicMin.
    // Key = (sortable_dist << 32) | col  -> min picks smallest dist, ties -> lowest index
#pragma unroll
    for (int i = 0; i < TM; i++) {
        float v = acc[i][0];
        int   c = 0;
#pragma unroll
        for (int j = 1; j < TN; j++) {
            if (acc[i][j] < v) { v = acc[i][j]; c = j; }
        }
        unsigned long long key =
            ((unsigned long long)float_to_sortable(v) << 32) |
            (unsigned int)(n0 + tx * TN + c);
        // butterfly over the 16 tx-lanes (lanes 0-15 / 16-31 are independent rows)
#pragma unroll
        for (int o = 8; o >= 1; o >>= 1) {
            unsigned long long other = __shfl_xor_sync(0xFFFFFFFFu, key, o);
            if (other < key) key = other;
        }
        if (tx == 0) {
            atomicMin(&g_best[m0 + ty * TM + i], key);
        }
    }
}

// Gaussian-window weighted gather. blockDim = (64, 4): 64 threads x float4 per sample.
__global__ __launch_bounds__(256)
void wknn_gather_kernel(const float* __restrict__ W, float* __restrict__ out) {
    const int b = blockIdx.x * 4 + threadIdx.y;
    const int e4 = threadIdx.x;  // float4 index: dims [4*e4, 4*e4+3]

    const int ix = (int)(g_best[b] & 0xFFFFFFFFu);
    const bool left_edge = (ix - KNN) < 0;

    float4 acc = make_float4(0.f, 0.f, 0.f, 0.f);
    float wsum = 0.f;

#pragma unroll
    for (int d = -KNN; d <= KNN; d++) {
        int idx = ix + d;
        bool valid = (idx >= 0) && (idx < NVEC) && (!left_edge || d < KNN);
        if (valid) {
            float g = expf(-0.5f * (float)(d * d));
            wsum += g;
            float4 v = *(const float4*)(W + (long long)idx * EDIM + e4 * 4);
            acc.x = fmaf(g, v.x, acc.x);
            acc.y = fmaf(g, v.y, acc.y);
            acc.z = fmaf(g, v.z, acc.z);
            acc.w = fmaf(g, v.w, acc.w);
        }
    }
    float inv = 1.0f / wsum;
    acc.x *= inv; acc.y *= inv; acc.z *= inv; acc.w *= inv;
    *(float4*)(out + (long long)b * EDIM + e4 * 4) = acc;
}

extern "C" void kernel_launch(void* const* d_in, const int* in_sizes, int n_in,
                              void* d_out, int out_size) {
    const float* x = (const float*)d_in[0];   // [32768, 256]
    const float* W = (const float*)d_in[1];   // [4096, 256]
    float* out = (float*)d_out;               // [32768, 256]

    init_best_kernel<<<(BATCH + 255) / 256, 256>>>();

    dim3 grid(NVEC / BN, BATCH / BM);  // (32, 256)
    dist_argmin_kernel<<<grid, 256>>>(x, W);

    dim3 gblock(64, 4);
    wknn_gather_kernel<<<BATCH / 4, gblock>>>(W, out);
}

// round 5
// speedup vs baseline: 2.8210x; 2.8210x over previous
#include <cuda_runtime.h>
#include <cuda_fp16.h>
#include <cstdint>

#define BATCH 32768
#define NVEC  4096
#define EDIM  256
#define KNN   20
#define CAP   64
#define MARGIN 0.5f

#define BM 128
#define BN 128
#define PADK 264          // fp16 elems per padded smem row
#define ROWB (PADK * 2)   // 528 bytes

// smem offsets (bytes)
#define SM_A   0
#define SM_B0  67584
#define SM_B1  135168
#define SM_MIN 202752
#define SMEM_BYTES 203264

__device__ __half g_xh[BATCH * EDIM];
__device__ __half g_wh[NVEC * EDIM];
__device__ int    g_cnt[BATCH];
__device__ int    g_rec[BATCH * CAP];
__device__ int    g_best[BATCH];

// ---------------- helpers ----------------
__device__ __forceinline__ uint32_t smem_u32(const void* p) {
    uint32_t a;
    asm("{ .reg .u64 t; cvta.to.shared.u64 t, %1; cvt.u32.u64 %0, t; }" : "=r"(a) : "l"(p));
    return a;
}
__device__ __forceinline__ void cp16(uint32_t dst, const void* src) {
    asm volatile("cp.async.cg.shared.global [%0], [%1], 16;" :: "r"(dst), "l"(src));
}
#define CP_COMMIT() asm volatile("cp.async.commit_group;" ::: "memory")
#define CP_WAIT(n)  asm volatile("cp.async.wait_group %0;" :: "n"(n) : "memory")

__device__ __forceinline__ void ldsm_x4(uint32_t* r, uint32_t addr) {
    asm volatile("ldmatrix.sync.aligned.m8n8.x4.shared.b16 {%0,%1,%2,%3}, [%4];"
                 : "=r"(r[0]), "=r"(r[1]), "=r"(r[2]), "=r"(r[3]) : "r"(addr));
}
__device__ __forceinline__ void mma16816(float* c, const uint32_t* a, const uint32_t* b) {
    asm volatile("mma.sync.aligned.m16n8k16.row.col.f32.f16.f16.f32 "
                 "{%0,%1,%2,%3}, {%4,%5,%6,%7}, {%8,%9}, {%0,%1,%2,%3};"
                 : "+f"(c[0]), "+f"(c[1]), "+f"(c[2]), "+f"(c[3])
                 : "r"(a[0]), "r"(a[1]), "r"(a[2]), "r"(a[3]), "r"(b[0]), "r"(b[1]));
}
__device__ __forceinline__ unsigned sortable(float f) {
    unsigned u = __float_as_uint(f);
    return (u & 0x80000000u) ? ~u : (u | 0x80000000u);
}
__device__ __forceinline__ float unsortable(unsigned u) {
    unsigned b = (u & 0x80000000u) ? (u & 0x7FFFFFFFu) : ~u;
    return __uint_as_float(b);
}

// ---------------- prep: fp32 -> fp16, zero counters ----------------
__global__ __launch_bounds__(256)
void prep_kernel(const float* __restrict__ x, const float* __restrict__ W) {
    const int nx = BATCH * EDIM / 2;
    const int nw = NVEC * EDIM / 2;
    int i = blockIdx.x * blockDim.x + threadIdx.x;
    if (i < nx) {
        float2 v = ((const float2*)x)[i];
        ((__half2*)g_xh)[i] = __floats2half2_rn(v.x, v.y);
    } else if (i < nx + nw) {
        int j = i - nx;
        float2 v = ((const float2*)W)[j];
        ((__half2*)g_wh)[j] = __floats2half2_rn(v.x, v.y);
    }
}
__global__ __launch_bounds__(256)
void zero_cnt_kernel() {
    int i = blockIdx.x * blockDim.x + threadIdx.x;
    if (i < BATCH) g_cnt[i] = 0;
}

// ---------------- fp16 GEMM + margin-candidate collection ----------------
// CTA: 128 rows x (loop 32 tiles of 128 cols). 8 warps: 2(m) x 4(n), warp tile 64x32.
__global__ __launch_bounds__(256, 1)
void gemm_cand_kernel() {
    extern __shared__ char smem[];
    const uint32_t sb = smem_u32(smem);
    unsigned* sMin = (unsigned*)(smem + SM_MIN);

    const int tid  = threadIdx.x;
    const int lane = tid & 31;
    const int wid  = tid >> 5;
    const int wm   = wid >> 2;   // 0..1
    const int wn   = wid & 3;    // 0..3
    const int m0   = blockIdx.x * BM;

    if (tid < 128) sMin[tid] = 0xFFFFFFFFu;

    // load A (once, 128x256 fp16) and B tile 0 via cp.async
    {
        const char* srcA = (const char*)g_xh + (size_t)m0 * 512;
        for (int i = tid; i < 4096; i += 256) {
            int r = i >> 5, g = i & 31;
            cp16(sb + SM_A + r * ROWB + g * 16, srcA + r * 512 + g * 16);
        }
        const char* srcB = (const char*)g_wh;
        for (int i = tid; i < 4096; i += 256) {
            int r = i >> 5, g = i & 31;
            cp16(sb + SM_B0 + r * ROWB + g * 16, srcB + r * 512 + g * 16);
        }
    }
    CP_COMMIT();

    const uint32_t aoff = (uint32_t)((wm * 64 + (lane & 15)) * ROWB + ((lane & 16) ? 16 : 0));
    const uint32_t boff = (uint32_t)((wn * 32 + (lane & 7) + ((lane & 16) ? 8 : 0)) * ROWB +
                                     ((lane & 8) ? 16 : 0));

    for (int nc = 0; nc < NVEC / BN; nc++) {
        if (nc < NVEC / BN - 1) {
            const char* srcB = (const char*)g_wh + (size_t)(nc + 1) * 128 * 512;
            const uint32_t dstB = sb + ((nc & 1) ? SM_B0 : SM_B1);
            for (int i = tid; i < 4096; i += 256) {
                int r = i >> 5, g = i & 31;
                cp16(dstB + r * ROWB + g * 16, srcB + r * 512 + g * 16);
            }
            CP_COMMIT();
            CP_WAIT(1);
        } else {
            CP_WAIT(0);
        }
        __syncthreads();

        const uint32_t sB = sb + ((nc & 1) ? SM_B1 : SM_B0);

        float c[4][4][4];
#pragma unroll
        for (int mt = 0; mt < 4; mt++)
#pragma unroll
            for (int nt = 0; nt < 4; nt++)
#pragma unroll
                for (int q = 0; q < 4; q++) c[mt][nt][q] = 0.0f;

#pragma unroll
        for (int ks = 0; ks < 16; ks++) {
            uint32_t af[4][4];
#pragma unroll
            for (int mt = 0; mt < 4; mt++)
                ldsm_x4(af[mt], sb + SM_A + aoff + mt * (16 * ROWB) + ks * 32);
            uint32_t bf[4][2];
#pragma unroll
            for (int p = 0; p < 2; p++) {
                uint32_t t[4];
                ldsm_x4(t, sB + boff + p * (16 * ROWB) + ks * 32);
                bf[2 * p][0] = t[0]; bf[2 * p][1] = t[1];
                bf[2 * p + 1][0] = t[2]; bf[2 * p + 1][1] = t[3];
            }
#pragma unroll
            for (int mt = 0; mt < 4; mt++)
#pragma unroll
                for (int nt = 0; nt < 4; nt++)
                    mma16816(c[mt][nt], af[mt], bf[nt]);
        }

        // ---- per-row running min + margin-candidate appends ----
        float rmin[4][2];
#pragma unroll
        for (int mt = 0; mt < 4; mt++) {
#pragma unroll
            for (int rr = 0; rr < 2; rr++) {
                float m = fminf(c[mt][0][2 * rr], c[mt][0][2 * rr + 1]);
#pragma unroll
                for (int nt = 1; nt < 4; nt++)
                    m = fminf(m, fminf(c[mt][nt][2 * rr], c[mt][nt][2 * rr + 1]));
                m = fminf(m, __shfl_xor_sync(0xFFFFFFFFu, m, 1));
                m = fminf(m, __shfl_xor_sync(0xFFFFFFFFu, m, 2));
                rmin[mt][rr] = m;
            }
        }
        if ((lane & 3) == 0) {
#pragma unroll
            for (int mt = 0; mt < 4; mt++)
#pragma unroll
                for (int rr = 0; rr < 2; rr++) {
                    int row = wm * 64 + mt * 16 + (lane >> 2) + rr * 8;
                    atomicMin(&sMin[row], sortable(rmin[mt][rr]));
                }
        }
        __syncthreads();  // also gates next-iter cp.async buffer overwrite

        float thr[4][2];
#pragma unroll
        for (int mt = 0; mt < 4; mt++)
#pragma unroll
            for (int rr = 0; rr < 2; rr++) {
                int row = wm * 64 + mt * 16 + (lane >> 2) + rr * 8;
                thr[mt][rr] = unsortable(sMin[row]) + MARGIN;
            }
#pragma unroll
        for (int mt = 0; mt < 4; mt++)
#pragma unroll
            for (int nt = 0; nt < 4; nt++)
#pragma unroll
                for (int q = 0; q < 4; q++) {
                    float v = c[mt][nt][q];
                    int rr = q >> 1;
                    if (v < thr[mt][rr]) {
                        int grow = m0 + wm * 64 + mt * 16 + (lane >> 2) + rr * 8;
                        int n = nc * BN + wn * 32 + nt * 8 + 2 * (lane & 3) + (q & 1);
                        int p = atomicAdd(&g_cnt[grow], 1);
                        if (p < CAP) g_rec[grow * CAP + p] = n;
                    }
                }
    }
}

// ---------------- exact rescore, ONE THREAD PER ROW ----------------
// Distance arithmetic replicates R1's passing kernel bit-for-bit: a single
// fp32 fmaf chain over k ascending (float4 loads, components in order).
__global__ __launch_bounds__(256)
void rescore_kernel(const float* __restrict__ x, const float* __restrict__ W) {
    const int row = blockIdx.x * blockDim.x + threadIdx.x;
    const float4* xr = (const float4*)(x + (size_t)row * EDIM);

    const int cnt = g_cnt[row];
    unsigned long long best = 0xFFFFFFFFFFFFFFFFULL;

    if (cnt <= CAP) {
        for (int i = 0; i < cnt; i++) {
            int n = g_rec[row * CAP + i];
            const float4* wr = (const float4*)(W + (size_t)n * EDIM);
            float d = 0.0f;
#pragma unroll 4
            for (int k = 0; k < EDIM / 4; k++) {
                float4 a = xr[k];
                float4 b = wr[k];
                d = fmaf(a.x, b.x, d);
                d = fmaf(a.y, b.y, d);
                d = fmaf(a.z, b.z, d);
                d = fmaf(a.w, b.w, d);
            }
            unsigned long long key = ((unsigned long long)sortable(d) << 32) | (unsigned)n;
            if (key < best) best = key;
        }
    } else {
        for (int n = 0; n < NVEC; n++) {  // overflow fallback (exact, same order)
            const float4* wr = (const float4*)(W + (size_t)n * EDIM);
            float d = 0.0f;
            for (int k = 0; k < EDIM / 4; k++) {
                float4 a = xr[k];
                float4 b = wr[k];
                d = fmaf(a.x, b.x, d);
                d = fmaf(a.y, b.y, d);
                d = fmaf(a.z, b.z, d);
                d = fmaf(a.w, b.w, d);
            }
            unsigned long long key = ((unsigned long long)sortable(d) << 32) | (unsigned)n;
            if (key < best) best = key;
        }
    }
    g_best[row] = (int)(best & 0xFFFFFFFFu);
}

// ---------------- Gaussian-window weighted gather (proven in R1) ----------------
__global__ __launch_bounds__(256)
void wknn_gather_kernel(const float* __restrict__ W, float* __restrict__ out) {
    const int b = blockIdx.x * 4 + threadIdx.y;
    const int e4 = threadIdx.x;

    const int ix = g_best[b];
    const bool left_edge = (ix - KNN) < 0;

    float4 acc = make_float4(0.f, 0.f, 0.f, 0.f);
    float wsum = 0.f;

#pragma unroll
    for (int d = -KNN; d <= KNN; d++) {
        int idx = ix + d;
        bool valid = (idx >= 0) && (idx < NVEC) && (!left_edge || d < KNN);
        if (valid) {
            float g = expf(-0.5f * (float)(d * d));
            wsum += g;
            float4 v = *(const float4*)(W + (long long)idx * EDIM + e4 * 4);
            acc.x = fmaf(g, v.x, acc.x);
            acc.y = fmaf(g, v.y, acc.y);
            acc.z = fmaf(g, v.z, acc.z);
            acc.w = fmaf(g, v.w, acc.w);
        }
    }
    float inv = 1.0f / wsum;
    acc.x *= inv; acc.y *= inv; acc.z *= inv; acc.w *= inv;
    *(float4*)(out + (long long)b * EDIM + e4 * 4) = acc;
}

// ---------------- host ----------------
extern "C" void kernel_launch(void* const* d_in, const int* in_sizes, int n_in,
                              void* d_out, int out_size) {
    const float* x = (const float*)d_in[0];   // [32768, 256]
    const float* W = (const float*)d_in[1];   // [4096, 256]
    float* out = (float*)d_out;               // [32768, 256]

    const int nconv = (BATCH * EDIM + NVEC * EDIM) / 2;
    prep_kernel<<<(nconv + 255) / 256, 256>>>(x, W);
    zero_cnt_kernel<<<BATCH / 256, 256>>>();

    cudaFuncSetAttribute(gemm_cand_kernel,
                         cudaFuncAttributeMaxDynamicSharedMemorySize, SMEM_BYTES);
    gemm_cand_kernel<<<BATCH / BM, 256, SMEM_BYTES>>>();

    rescore_kernel<<<BATCH / 256, 256>>>(x, W);

    dim3 gblock(64, 4);
    wknn_gather_kernel<<<BATCH / 4, gblock>>>(W, out);
}

// round 6
// speedup vs baseline: 3.3981x; 1.2046x over previous
#include <cuda_runtime.h>
#include <cuda_fp16.h>
#include <cstdint>

#define BATCH 32768
#define NVEC  4096
#define EDIM  256
#define KNN   20
#define CAP   64
#define MARGIN 0.5f
#define FILT  0.3f        // 2 x conservative fp16-dot error bound

#define BM 128
#define BN 128
#define PADK 264          // fp16 elems per padded smem row
#define ROWB (PADK * 2)   // 528 bytes

// smem offsets (bytes)
#define SM_A   0
#define SM_B0  67584
#define SM_B1  135168
#define SM_MIN 202752
#define SMEM_BYTES 203264

__device__ __half g_xh[BATCH * EDIM];
__device__ __half g_wh[NVEC * EDIM];
__device__ int    g_cnt[BATCH];
__device__ int    g_rec[BATCH * CAP];
__device__ float  g_recv[BATCH * CAP];
__device__ int    g_best[BATCH];
__device__ float  g_R[NVEC * EDIM];   // precomputed Gaussian-window results

// ---------------- helpers ----------------
__device__ __forceinline__ uint32_t smem_u32(const void* p) {
    uint32_t a;
    asm("{ .reg .u64 t; cvta.to.shared.u64 t, %1; cvt.u32.u64 %0, t; }" : "=r"(a) : "l"(p));
    return a;
}
__device__ __forceinline__ void cp16(uint32_t dst, const void* src) {
    asm volatile("cp.async.cg.shared.global [%0], [%1], 16;" :: "r"(dst), "l"(src));
}
#define CP_COMMIT() asm volatile("cp.async.commit_group;" ::: "memory")
#define CP_WAIT(n)  asm volatile("cp.async.wait_group %0;" :: "n"(n) : "memory")

__device__ __forceinline__ void ldsm_x4(uint32_t* r, uint32_t addr) {
    asm volatile("ldmatrix.sync.aligned.m8n8.x4.shared.b16 {%0,%1,%2,%3}, [%4];"
                 : "=r"(r[0]), "=r"(r[1]), "=r"(r[2]), "=r"(r[3]) : "r"(addr));
}
__device__ __forceinline__ void mma16816(float* c, const uint32_t* a, const uint32_t* b) {
    asm volatile("mma.sync.aligned.m16n8k16.row.col.f32.f16.f16.f32 "
                 "{%0,%1,%2,%3}, {%4,%5,%6,%7}, {%8,%9}, {%0,%1,%2,%3};"
                 : "+f"(c[0]), "+f"(c[1]), "+f"(c[2]), "+f"(c[3])
                 : "r"(a[0]), "r"(a[1]), "r"(a[2]), "r"(a[3]), "r"(b[0]), "r"(b[1]));
}
__device__ __forceinline__ unsigned sortable(float f) {
    unsigned u = __float_as_uint(f);
    return (u & 0x80000000u) ? ~u : (u | 0x80000000u);
}
__device__ __forceinline__ float unsortable(unsigned u) {
    unsigned b = (u & 0x80000000u) ? (u & 0x7FFFFFFFu) : ~u;
    return __uint_as_float(b);
}

// ---------------- prep: fp32 -> fp16 + zero counters (fused) ----------------
__global__ __launch_bounds__(256)
void prep_kernel(const float* __restrict__ x, const float* __restrict__ W) {
    const int nx = BATCH * EDIM / 2;
    const int nw = NVEC * EDIM / 2;
    int i = blockIdx.x * blockDim.x + threadIdx.x;
    if (i < nx) {
        float2 v = ((const float2*)x)[i];
        ((__half2*)g_xh)[i] = __floats2half2_rn(v.x, v.y);
    } else if (i < nx + nw) {
        int j = i - nx;
        float2 v = ((const float2*)W)[j];
        ((__half2*)g_wh)[j] = __floats2half2_rn(v.x, v.y);
    }
    if (i < BATCH) g_cnt[i] = 0;
}

// ---------------- fp16 GEMM + margin-candidate collection ----------------
// CTA: 128 rows x (loop 32 tiles of 128 cols). 8 warps: 2(m) x 4(n), warp tile 64x32.
__global__ __launch_bounds__(256, 1)
void gemm_cand_kernel() {
    extern __shared__ char smem[];
    const uint32_t sb = smem_u32(smem);
    unsigned* sMin = (unsigned*)(smem + SM_MIN);

    const int tid  = threadIdx.x;
    const int lane = tid & 31;
    const int wid  = tid >> 5;
    const int wm   = wid >> 2;   // 0..1
    const int wn   = wid & 3;    // 0..3
    const int m0   = blockIdx.x * BM;

    if (tid < 128) sMin[tid] = 0xFFFFFFFFu;

    {
        const char* srcA = (const char*)g_xh + (size_t)m0 * 512;
        for (int i = tid; i < 4096; i += 256) {
            int r = i >> 5, g = i & 31;
            cp16(sb + SM_A + r * ROWB + g * 16, srcA + r * 512 + g * 16);
        }
        const char* srcB = (const char*)g_wh;
        for (int i = tid; i < 4096; i += 256) {
            int r = i >> 5, g = i & 31;
            cp16(sb + SM_B0 + r * ROWB + g * 16, srcB + r * 512 + g * 16);
        }
    }
    CP_COMMIT();

    const uint32_t aoff = (uint32_t)((wm * 64 + (lane & 15)) * ROWB + ((lane & 16) ? 16 : 0));
    const uint32_t boff = (uint32_t)((wn * 32 + (lane & 7) + ((lane & 16) ? 8 : 0)) * ROWB +
                                     ((lane & 8) ? 16 : 0));

    for (int nc = 0; nc < NVEC / BN; nc++) {
        if (nc < NVEC / BN - 1) {
            const char* srcB = (const char*)g_wh + (size_t)(nc + 1) * 128 * 512;
            const uint32_t dstB = sb + ((nc & 1) ? SM_B0 : SM_B1);
            for (int i = tid; i < 4096; i += 256) {
                int r = i >> 5, g = i & 31;
                cp16(dstB + r * ROWB + g * 16, srcB + r * 512 + g * 16);
            }
            CP_COMMIT();
            CP_WAIT(1);
        } else {
            CP_WAIT(0);
        }
        __syncthreads();

        const uint32_t sB = sb + ((nc & 1) ? SM_B1 : SM_B0);

        float c[4][4][4];
#pragma unroll
        for (int mt = 0; mt < 4; mt++)
#pragma unroll
            for (int nt = 0; nt < 4; nt++)
#pragma unroll
                for (int q = 0; q < 4; q++) c[mt][nt][q] = 0.0f;

#pragma unroll
        for (int ks = 0; ks < 16; ks++) {
            uint32_t af[4][4];
#pragma unroll
            for (int mt = 0; mt < 4; mt++)
                ldsm_x4(af[mt], sb + SM_A + aoff + mt * (16 * ROWB) + ks * 32);
            uint32_t bf[4][2];
#pragma unroll
            for (int p = 0; p < 2; p++) {
                uint32_t t[4];
                ldsm_x4(t, sB + boff + p * (16 * ROWB) + ks * 32);
                bf[2 * p][0] = t[0]; bf[2 * p][1] = t[1];
                bf[2 * p + 1][0] = t[2]; bf[2 * p + 1][1] = t[3];
            }
#pragma unroll
            for (int mt = 0; mt < 4; mt++)
#pragma unroll
                for (int nt = 0; nt < 4; nt++)
                    mma16816(c[mt][nt], af[mt], bf[nt]);
        }

        // ---- per-row running min + margin-candidate appends ----
        float rmin[4][2];
#pragma unroll
        for (int mt = 0; mt < 4; mt++) {
#pragma unroll
            for (int rr = 0; rr < 2; rr++) {
                float m = fminf(c[mt][0][2 * rr], c[mt][0][2 * rr + 1]);
#pragma unroll
                for (int nt = 1; nt < 4; nt++)
                    m = fminf(m, fminf(c[mt][nt][2 * rr], c[mt][nt][2 * rr + 1]));
                m = fminf(m, __shfl_xor_sync(0xFFFFFFFFu, m, 1));
                m = fminf(m, __shfl_xor_sync(0xFFFFFFFFu, m, 2));
                rmin[mt][rr] = m;
            }
        }
        if ((lane & 3) == 0) {
#pragma unroll
            for (int mt = 0; mt < 4; mt++)
#pragma unroll
                for (int rr = 0; rr < 2; rr++) {
                    int row = wm * 64 + mt * 16 + (lane >> 2) + rr * 8;
                    atomicMin(&sMin[row], sortable(rmin[mt][rr]));
                }
        }
        __syncthreads();  // also gates next-iter cp.async buffer overwrite

        float thr[4][2];
#pragma unroll
        for (int mt = 0; mt < 4; mt++)
#pragma unroll
            for (int rr = 0; rr < 2; rr++) {
                int row = wm * 64 + mt * 16 + (lane >> 2) + rr * 8;
                thr[mt][rr] = unsortable(sMin[row]) + MARGIN;
            }
#pragma unroll
        for (int mt = 0; mt < 4; mt++)
#pragma unroll
            for (int nt = 0; nt < 4; nt++)
#pragma unroll
                for (int q = 0; q < 4; q++) {
                    float v = c[mt][nt][q];
                    int rr = q >> 1;
                    if (v < thr[mt][rr]) {
                        int grow = m0 + wm * 64 + mt * 16 + (lane >> 2) + rr * 8;
                        int n = nc * BN + wn * 32 + nt * 8 + 2 * (lane & 3) + (q & 1);
                        int p = atomicAdd(&g_cnt[grow], 1);
                        if (p < CAP) {
                            g_rec[grow * CAP + p] = n;
                            g_recv[grow * CAP + p] = v;
                        }
                    }
                }
    }
}

// ---------------- value-filtered rescore, one thread per row ----------------
// ~92% of rows: exactly one survivor after the 2E filter -> no dot products.
// Multi-survivor rows: exact fp32 dots in R1's proven ascending-k chain order.
__global__ __launch_bounds__(128)
void rescore_kernel(const float* __restrict__ x, const float* __restrict__ W) {
    const int row = blockIdx.x * blockDim.x + threadIdx.x;
    const int cnt = g_cnt[row];

    unsigned long long best = 0xFFFFFFFFFFFFFFFFULL;
    const float4* xr = (const float4*)(x + (size_t)row * EDIM);

    auto evalExact = [&](int n) {
        const float4* wr = (const float4*)(W + (size_t)n * EDIM);
        float d = 0.0f;
#pragma unroll 4
        for (int k = 0; k < EDIM / 4; k++) {
            float4 a = xr[k];
            float4 b = wr[k];
            d = fmaf(a.x, b.x, d);
            d = fmaf(a.y, b.y, d);
            d = fmaf(a.z, b.z, d);
            d = fmaf(a.w, b.w, d);
        }
        unsigned long long key = ((unsigned long long)sortable(d) << 32) | (unsigned)n;
        if (key < best) best = key;
    };

    if (cnt <= CAP) {
        // pass 1: min approx value among stored candidates
        float mv = __int_as_float(0x7F800000);
        for (int i = 0; i < cnt; i++) mv = fminf(mv, g_recv[row * CAP + i]);
        const float thr = mv + FILT;
        // pass 2: survivors
        int sc = 0, single = 0;
        for (int i = 0; i < cnt; i++) {
            if (g_recv[row * CAP + i] <= thr) { sc++; single = g_rec[row * CAP + i]; }
        }
        if (sc == 1) {
            g_best[row] = single;
            return;
        }
        for (int i = 0; i < cnt; i++) {
            if (g_recv[row * CAP + i] <= thr) evalExact(g_rec[row * CAP + i]);
        }
    } else {
        for (int n = 0; n < NVEC; n++) evalExact(n);  // overflow fallback (≈never)
    }
    g_best[row] = (int)(best & 0xFFFFFFFFu);
}

// ---------------- precompute Gaussian-window table R[ix] for all 4096 ix ----
__global__ __launch_bounds__(256)
void build_R_kernel(const float* __restrict__ W) {
    const int ix = blockIdx.x * 4 + threadIdx.y;
    const int e4 = threadIdx.x;
    const bool left_edge = (ix - KNN) < 0;

    float4 acc = make_float4(0.f, 0.f, 0.f, 0.f);
    float wsum = 0.f;

#pragma unroll
    for (int d = -KNN; d <= KNN; d++) {
        int idx = ix + d;
        bool valid = (idx >= 0) && (idx < NVEC) && (!left_edge || d < KNN);
        if (valid) {
            float g = expf(-0.5f * (float)(d * d));
            wsum += g;
            float4 v = *(const float4*)(W + (long long)idx * EDIM + e4 * 4);
            acc.x = fmaf(g, v.x, acc.x);
            acc.y = fmaf(g, v.y, acc.y);
            acc.z = fmaf(g, v.z, acc.z);
            acc.w = fmaf(g, v.w, acc.w);
        }
    }
    float inv = 1.0f / wsum;
    acc.x *= inv; acc.y *= inv; acc.z *= inv; acc.w *= inv;
    *(float4*)(g_R + (long long)ix * EDIM + e4 * 4) = acc;
}

// ---------------- scatter: out[b] = R[ix[b]]  (write-bound) ----------------
__global__ __launch_bounds__(256)
void scatter_kernel(float* __restrict__ out) {
    const int b = blockIdx.x * 4 + threadIdx.y;
    const int e4 = threadIdx.x;
    const int ix = g_best[b];
    float4 v = __ldg((const float4*)(g_R + (long long)ix * EDIM + e4 * 4));
    *(float4*)(out + (long long)b * EDIM + e4 * 4) = v;
}

// ---------------- host ----------------
extern "C" void kernel_launch(void* const* d_in, const int* in_sizes, int n_in,
                              void* d_out, int out_size) {
    const float* x = (const float*)d_in[0];   // [32768, 256]
    const float* W = (const float*)d_in[1];   // [4096, 256]
    float* out = (float*)d_out;               // [32768, 256]

    const int nconv = (BATCH * EDIM + NVEC * EDIM) / 2;
    prep_kernel<<<(nconv + 255) / 256, 256>>>(x, W);

    cudaFuncSetAttribute(gemm_cand_kernel,
                         cudaFuncAttributeMaxDynamicSharedMemorySize, SMEM_BYTES);
    gemm_cand_kernel<<<BATCH / BM, 256, SMEM_BYTES>>>();

    dim3 rblk(64, 4);
    build_R_kernel<<<NVEC / 4, rblk>>>(W);

    rescore_kernel<<<BATCH / 128, 128>>>(x, W);

    scatter_kernel<<<BATCH / 4, rblk>>>(out);
}